// round 13
// baseline (speedup 1.0000x reference)
#include <cuda_runtime.h>
#include <cuda_fp16.h>
#include <stdint.h>
#include <math.h>

// Problem constants
#define B_   32
#define Q_   20
#define T_   100
#define KDIM 512          // D == H == 512 (GEMM K dim)
#define H_   512
#define N_   (B_*Q_)      // 640 sequences
#define G_   (4*H_)       // 2048 gate columns (interleaved: jp = h*4 + gate)
#define M_   (N_*T_)      // 64000 rows of the x_gates GEMM

#define LDS_   40         // smem row stride (fp16 elems) for 32-wide k-chunks
#define CH     32         // k-chunk
#define NCHUNK (KDIM/CH)  // 16

// ---------------------------------------------------------------------------
// Static device scratch
// ---------------------------------------------------------------------------
__device__ __align__(16) float  g_xg[(size_t)M_ * G_];      // interleaved gate pre-acts
__device__ __align__(16) __half gX_hi[(size_t)M_ * KDIM];   // X in plain fp16 (2-term xg split)
__device__ __align__(16) __half gWih_hi[(size_t)G_ * KDIM]; // interleaved rows
__device__ __align__(16) __half gWih_lo[(size_t)G_ * KDIM];
__device__ __align__(16) __half gWhh_hi[(size_t)G_ * KDIM]; // interleaved rows
__device__ __align__(16) __half gWhh_lo[(size_t)G_ * KDIM];
__device__ float g_biasI[G_];                               // interleaved bih+bhh
__device__ __align__(16) __half g_h_hi[2][(size_t)N_ * H_];
__device__ __align__(16) __half g_h_lo[2][(size_t)N_ * H_];
__device__ float g_c[(size_t)N_ * H_];

// ---------------------------------------------------------------------------
// PTX helpers
// ---------------------------------------------------------------------------
__device__ __forceinline__ uint32_t smem_u32_of(const void* p) {
    uint32_t a;
    asm("{ .reg .u64 t; cvta.to.shared.u64 t, %1; cvt.u32.u64 %0, t; }" : "=r"(a) : "l"(p));
    return a;
}
__device__ __forceinline__ void cp16(uint32_t dst, const void* src) {
    asm volatile("cp.async.cg.shared.global [%0], [%1], 16;" :: "r"(dst), "l"(src));
}
__device__ __forceinline__ void cp_commit() {
    asm volatile("cp.async.commit_group;" ::: "memory");
}
template<int NN> __device__ __forceinline__ void cp_wait() {
    asm volatile("cp.async.wait_group %0;" :: "n"(NN) : "memory");
}
__device__ __forceinline__ void ldm4(uint32_t addr, uint32_t* r) {
    asm volatile("ldmatrix.sync.aligned.m8n8.x4.shared.b16 {%0,%1,%2,%3}, [%4];"
        : "=r"(r[0]), "=r"(r[1]), "=r"(r[2]), "=r"(r[3]) : "r"(addr));
}
__device__ __forceinline__ void mma16816(float* c, const uint32_t* a, const uint32_t* b) {
    asm volatile("mma.sync.aligned.m16n8k16.row.col.f32.f16.f16.f32 "
        "{%0,%1,%2,%3}, {%4,%5,%6,%7}, {%8,%9}, {%0,%1,%2,%3};"
        : "+f"(c[0]), "+f"(c[1]), "+f"(c[2]), "+f"(c[3])
        : "r"(a[0]), "r"(a[1]), "r"(a[2]), "r"(a[3]), "r"(b[0]), "r"(b[1]));
}
__device__ __forceinline__ void f2split(float x, __half& hi, __half& lo) {
    hi = __float2half_rn(x);
    lo = __float2half_rn(x - __half2float(hi));
}

// ---------------------------------------------------------------------------
// Setup kernels
// ---------------------------------------------------------------------------
__global__ void init_state_kernel() {
    int idx = blockIdx.x * blockDim.x + threadIdx.x;
    if (idx < N_ * H_) {
        g_h_hi[0][idx] = __float2half_rn(0.0f);
        g_h_lo[0][idx] = __float2half_rn(0.0f);
        g_c[idx] = 0.0f;
    }
}

__global__ void conv_x_kernel(const float* __restrict__ X) {
    size_t base = ((size_t)blockIdx.x * blockDim.x + threadIdx.x) * 4;
    if (base < (size_t)M_ * KDIM) {
        float4 v = *(const float4*)(X + base);
        __half2 p0 = make_half2(__float2half_rn(v.x), __float2half_rn(v.y));
        __half2 p1 = make_half2(__float2half_rn(v.z), __float2half_rn(v.w));
        *(__half2*)(gX_hi + base)     = p0;
        *(__half2*)(gX_hi + base + 2) = p1;
    }
}

__global__ void conv_w_kernel(const float* __restrict__ Wih,
                              const float* __restrict__ Whh,
                              const float* __restrict__ bih,
                              const float* __restrict__ bhh) {
    int jp = blockIdx.x;                 // interleaved dst row 0..2047
    int gate = jp & 3, h = jp >> 2;
    int j = gate * H_ + h;               // source row
    const float* si = Wih + (size_t)j * KDIM;
    const float* sh = Whh + (size_t)j * KDIM;
    for (int k = threadIdx.x; k < KDIM; k += blockDim.x) {
        __half hi, lo;
        f2split(si[k], hi, lo);
        gWih_hi[(size_t)jp * KDIM + k] = hi; gWih_lo[(size_t)jp * KDIM + k] = lo;
        f2split(sh[k], hi, lo);
        gWhh_hi[(size_t)jp * KDIM + k] = hi; gWhh_lo[(size_t)jp * KDIM + k] = lo;
    }
    if (threadIdx.x == 0) g_biasI[jp] = bih[j] + bhh[j];
}

// ---------------------------------------------------------------------------
// x_gates GEMM: 128x128 tile, grid (16, 500), 3-stage, 2 CTAs/SM (as R11).
// A = X plain fp16; B = W_ih hi+lo. D = A*Bh + A*Bl (2-term split).
// ---------------------------------------------------------------------------
#define XG_STAGE 30720
#define XG_SMEM  (XG_STAGE * 3)    // 92160

__global__ __launch_bounds__(256, 2)
void xg_mma_kernel() {
    extern __shared__ char smem[];
    const uint32_t sb = smem_u32_of(smem);
    __shared__ float bias_s[128];
    const int tid = threadIdx.x;
    const int j0 = blockIdx.x * 128;
    const int m0 = blockIdx.y * 128;
    if (tid < 128) bias_s[tid] = g_biasI[j0 + tid];

    const __half* Ah = gX_hi   + (size_t)m0 * KDIM;
    const __half* Bh = gWih_hi + (size_t)j0 * KDIM;
    const __half* Bl = gWih_lo + (size_t)j0 * KDIM;

    const int lane = tid & 31, wid = tid >> 5;
    const int mw = (wid & 1) * 64, nw = (wid >> 1) * 32;
    const int a_row = mw + (lane & 15);
    const int a_col = (lane >> 4) * 8;
    const int b_row = nw + ((lane >> 4) << 3) + (lane & 7);
    const int b_col = ((lane >> 3) & 1) * 8;

    float acc[4][4][4];
    #pragma unroll
    for (int a = 0; a < 4; ++a)
        #pragma unroll
        for (int b = 0; b < 4; ++b)
            #pragma unroll
            for (int d = 0; d < 4; ++d) acc[a][b][d] = 0.0f;

    #define XLOAD(stg, kc) do {                                          \
        uint32_t _b = sb + (uint32_t)(stg) * XG_STAGE;                   \
        _Pragma("unroll")                                                \
        for (int u = tid; u < 512; u += 256) {                           \
            int r_ = u >> 2, cg_ = (u & 3) * 8;                          \
            cp16(_b + (uint32_t)(r_ * LDS_ + cg_) * 2,                   \
                 Ah + (size_t)r_ * KDIM + (kc) + cg_);                   \
        }                                                                \
        _Pragma("unroll")                                                \
        for (int u = tid; u < 512; u += 256) {                           \
            int r_ = u >> 2, cg_ = (u & 3) * 8;                          \
            uint32_t d_ = _b + 10240 + (uint32_t)(r_ * LDS_ + cg_) * 2;  \
            size_t g_ = (size_t)r_ * KDIM + (kc) + cg_;                  \
            cp16(d_,         Bh + g_);                                   \
            cp16(d_ + 10240, Bl + g_);                                   \
        }                                                                \
    } while (0)

    XLOAD(0, 0);      cp_commit();
    XLOAD(1, CH);     cp_commit();

    #pragma unroll 1
    for (int c = 0; c < NCHUNK; ++c) {
        cp_wait<1>();
        __syncthreads();
        if (c + 2 < NCHUNK) XLOAD((c + 2) % 3, (c + 2) * CH);
        cp_commit();

        const uint32_t base = sb + (uint32_t)(c % 3) * XG_STAGE;
        #pragma unroll
        for (int kk = 0; kk < CH; kk += 16) {
            uint32_t ra[4][4], rbh[2][4], rbl[2][4];
            #pragma unroll
            for (int mi = 0; mi < 4; ++mi) {
                uint32_t aa = base + (uint32_t)((a_row + mi * 16) * LDS_ + kk + a_col) * 2;
                ldm4(aa, ra[mi]);
            }
            #pragma unroll
            for (int nj = 0; nj < 2; ++nj) {
                uint32_t ba = base + 10240 + (uint32_t)((b_row + nj * 16) * LDS_ + kk + b_col) * 2;
                ldm4(ba, rbh[nj]);
                ldm4(ba + 10240, rbl[nj]);
            }
            #pragma unroll
            for (int mi = 0; mi < 4; ++mi) {
                #pragma unroll
                for (int b8 = 0; b8 < 4; ++b8) {
                    const uint32_t* bh = &rbh[b8 >> 1][(b8 & 1) * 2];
                    const uint32_t* bl = &rbl[b8 >> 1][(b8 & 1) * 2];
                    mma16816(acc[mi][b8], ra[mi], bh);   // a*hi
                    mma16816(acc[mi][b8], ra[mi], bl);   // a*lo
                }
            }
        }
    }
    #undef XLOAD

    #pragma unroll
    for (int mi = 0; mi < 4; ++mi) {
        #pragma unroll
        for (int h2 = 0; h2 < 2; ++h2) {
            const int r = m0 + mw + mi * 16 + (lane >> 2) + h2 * 8;
            float* dst = g_xg + (size_t)r * G_ + j0;
            #pragma unroll
            for (int ni = 0; ni < 4; ++ni) {
                const int cc = nw + ni * 8 + (lane & 3) * 2;
                float2 v = make_float2(acc[mi][ni][h2 * 2 + 0] + bias_s[cc],
                                       acc[mi][ni][h2 * 2 + 1] + bias_s[cc + 1]);
                *(float2*)(dst + cc) = v;
            }
        }
    }
}

// ---------------------------------------------------------------------------
// Step kernel: 128x128 tile (128 rows x 32 h-cols x 4 gates). Grid (16, 5) =
// 80 CTAs, 1 per SM, single wave, identical tiles. Halves L2 traffic vs the
// 64-col tiling (h read by 16 jb blocks instead of 32).
// 3-term split (recurrent errors compound). CH=32, 3-stage pipeline.
// Stage (elems): Hhi[128*40] Hlo[128*40] Whi[128*40] Wlo[128*40] = 40960 B
// smem map: [0 .. 3*40960)  pipeline stages (reused for C staging)
//           [122880 .. +65536)  xg tile [128][128] fp32
// xg tile is loaded in stage-1's commit group (doesn't gate chunk 0).
// ---------------------------------------------------------------------------
#define SP_STAGE  40960
#define SP_XGOFF  (3 * SP_STAGE)            // 122880
#define STEP_SMEM (SP_XGOFF + 128*128*4)    // 188416

__global__ __launch_bounds__(256, 1)
void step_mma_kernel(float* __restrict__ out, int t) {
    extern __shared__ char smem[];
    const uint32_t sb = smem_u32_of(smem);
    const int tid = threadIdx.x;
    const int jb = blockIdx.x;           // 0..15
    const int j0 = jb * 128;             // interleaved gate-col base
    const int hb = jb * 32;              // h-col base
    const int n0 = blockIdx.y * 128;     // row base
    const int lane = tid & 31, wid = tid >> 5;
    const int wm = wid & 1, wn = wid >> 1;

    const int cur = t & 1, nxt = cur ^ 1;
    const __half* Hh = g_h_hi[cur] + (size_t)n0 * H_;
    const __half* Hl = g_h_lo[cur] + (size_t)n0 * H_;
    const __half* Wh = gWhh_hi + (size_t)j0 * KDIM;
    const __half* Wl = gWhh_lo + (size_t)j0 * KDIM;

    const int a_row = wm * 64 + (lane & 15);
    const int a_col = (lane >> 4) * 8;
    const int b_row = wn * 32 + ((lane >> 4) << 3) + (lane & 7);
    const int b_col = ((lane >> 3) & 1) * 8;

    float acc[4][4][4];
    #pragma unroll
    for (int a = 0; a < 4; ++a)
        #pragma unroll
        for (int b = 0; b < 4; ++b)
            #pragma unroll
            for (int d = 0; d < 4; ++d) acc[a][b][d] = 0.0f;

    // chunk loader: 128 rows h (hi+lo) + 128 rows W (hi+lo), 32 k each
    #define SLOAD(stg, kc) do {                                              \
        uint32_t _b = sb + (uint32_t)(stg) * SP_STAGE;                       \
        _Pragma("unroll")                                                    \
        for (int u = tid; u < 512; u += 256) {                               \
            int r_ = u >> 2, cg_ = (u & 3) * 8;                              \
            uint32_t d_ = _b + (uint32_t)(r_ * LDS_ + cg_) * 2;              \
            size_t gh_ = (size_t)r_ * H_ + (kc) + cg_;                       \
            size_t gw_ = (size_t)r_ * KDIM + (kc) + cg_;                     \
            cp16(d_,         Hh + gh_);                                      \
            cp16(d_ + 10240, Hl + gh_);                                      \
            cp16(d_ + 20480, Wh + gw_);                                      \
            cp16(d_ + 30720, Wl + gw_);                                      \
        }                                                                    \
    } while (0)

    // G0: stage 0.  G1: stage 1 + the xg tile (gates chunk 1, not chunk 0).
    SLOAD(0, 0);
    cp_commit();
    SLOAD(1, CH);
    #pragma unroll
    for (int u = tid; u < 128 * 32; u += 256) {
        int r = u >> 5, cg = (u & 31) * 4;
        cp16(sb + SP_XGOFF + (uint32_t)(r * 128 + cg) * 4,
             g_xg + ((size_t)(n0 + r) * T_ + t) * G_ + j0 + cg);
    }
    cp_commit();

    #pragma unroll 1
    for (int c = 0; c < NCHUNK; ++c) {
        cp_wait<1>();             // chunk c complete (in-order group retire)
        __syncthreads();          // all warps done with the buffer being refilled
        if (c + 2 < NCHUNK) SLOAD((c + 2) % 3, (c + 2) * CH);
        cp_commit();              // uniform accounting (possibly empty)

        const uint32_t base = sb + (uint32_t)(c % 3) * SP_STAGE;
        #pragma unroll
        for (int kk = 0; kk < CH; kk += 16) {
            uint32_t ra[4][4], rl[4][4], rbh[2][4], rbl[2][4];
            #pragma unroll
            for (int mi = 0; mi < 4; ++mi) {
                uint32_t aa = base + (uint32_t)((a_row + mi * 16) * LDS_ + kk + a_col) * 2;
                ldm4(aa, ra[mi]);
                ldm4(aa + 10240, rl[mi]);
            }
            #pragma unroll
            for (int nj = 0; nj < 2; ++nj) {
                uint32_t ba = base + 20480 + (uint32_t)((b_row + nj * 16) * LDS_ + kk + b_col) * 2;
                ldm4(ba, rbh[nj]);
                ldm4(ba + 10240, rbl[nj]);
            }
            #pragma unroll
            for (int mi = 0; mi < 4; ++mi) {
                #pragma unroll
                for (int b8 = 0; b8 < 4; ++b8) {
                    const uint32_t* bhp = &rbh[b8 >> 1][(b8 & 1) * 2];
                    const uint32_t* blp = &rbl[b8 >> 1][(b8 & 1) * 2];
                    mma16816(acc[mi][b8], ra[mi], bhp);   // hi*hi
                    mma16816(acc[mi][b8], ra[mi], blp);   // hi*lo
                    mma16816(acc[mi][b8], rl[mi], bhp);   // lo*hi
                }
            }
        }
    }
    #undef SLOAD

    // all warps done reading stage buffers before C staging reuses them
    __syncthreads();

    // stage C tile [128][132] fp32 in the stage region (xg tile untouched)
    float* Cs = (float*)smem;
    #pragma unroll
    for (int mi = 0; mi < 4; ++mi) {
        #pragma unroll
        for (int b8 = 0; b8 < 4; ++b8) {
            const int r = wm * 64 + mi * 16 + (lane >> 2);
            const int cc = wn * 32 + b8 * 8 + (lane & 3) * 2;
            *(float2*)&Cs[r * 132 + cc]       = make_float2(acc[mi][b8][0], acc[mi][b8][1]);
            *(float2*)&Cs[(r + 8) * 132 + cc] = make_float2(acc[mi][b8][2], acc[mi][b8][3]);
        }
    }
    __syncthreads();

    // fused LSTM cell update: 16 cells/thread (128 rows x 32 h-cols)
    const float* xgS = (const float*)(smem + SP_XGOFF);
    const bool last = (t == T_ - 1);
    const int hl = tid & 31;             // h lane 0..31
    const int rg = tid >> 5;             // row group 0..7
    #pragma unroll
    for (int e = 0; e < 16; ++e) {
        const int r = rg + e * 8;
        const int gn = n0 + r;
        float4 cg = *(const float4*)&Cs[r * 132 + hl * 4];
        float4 xv = *(const float4*)&xgS[r * 128 + hl * 4];
        float ig = cg.x + xv.x, fg = cg.y + xv.y;
        float gg = cg.z + xv.z, og = cg.w + xv.w;

        float is = 1.0f / (1.0f + __expf(-ig));
        float fs = 1.0f / (1.0f + __expf(-fg));
        float gt = tanhf(gg);
        float os = 1.0f / (1.0f + __expf(-og));

        const size_t ci = (size_t)gn * H_ + hb + hl;
        float c = fs * g_c[ci] + is * gt;
        g_c[ci] = c;
        float hv = os * tanhf(c);
        if (last) {
            out[ci] = hv;
        } else {
            __half hi, lo;
            f2split(hv, hi, lo);
            g_h_hi[nxt][ci] = hi;
            g_h_lo[nxt][ci] = lo;
        }
    }
}

// ---------------------------------------------------------------------------
// Launch
// ---------------------------------------------------------------------------
extern "C" void kernel_launch(void* const* d_in, const int* in_sizes, int n_in,
                              void* d_out, int out_size)
{
    const float* X   = (const float*)d_in[0];   // [B,Q,T,D] == [N*T, D]
    const float* Wih = (const float*)d_in[1];   // [4H, D]
    const float* Whh = (const float*)d_in[2];   // [4H, H]
    const float* bih = (const float*)d_in[3];   // [4H]
    const float* bhh = (const float*)d_in[4];   // [4H]
    float* out = (float*)d_out;                 // [B,Q,H] == [N, H]

    cudaFuncSetAttribute(xg_mma_kernel,   cudaFuncAttributeMaxDynamicSharedMemorySize, XG_SMEM);
    cudaFuncSetAttribute(step_mma_kernel, cudaFuncAttributeMaxDynamicSharedMemorySize, STEP_SMEM);

    init_state_kernel<<<(N_ * H_ + 255) / 256, 256>>>();
    conv_x_kernel<<<(int)(((size_t)M_ * KDIM / 4 + 255) / 256), 256>>>(X);
    conv_w_kernel<<<G_, 256>>>(Wih, Whh, bih, bhh);

    xg_mma_kernel<<<dim3(G_ / 128, M_ / 128), 256, XG_SMEM>>>();

    for (int t = 0; t < T_; ++t) {
        step_mma_kernel<<<dim3(16, 5), 256, STEP_SMEM>>>(out, t);
    }
}

// round 14
// speedup vs baseline: 1.0805x; 1.0805x over previous
#include <cuda_runtime.h>
#include <cuda_fp16.h>
#include <stdint.h>
#include <math.h>

// Problem constants
#define B_   32
#define Q_   20
#define T_   100
#define KDIM 512          // D == H == 512 (GEMM K dim)
#define H_   512
#define N_   (B_*Q_)      // 640 sequences
#define G_   (4*H_)       // 2048 gate columns (interleaved: jp = h*4 + gate)
#define M_   (N_*T_)      // 64000 rows of the x_gates GEMM

#define LDS_   40         // smem row stride (fp16 elems) for 32-wide k-chunks
#define CH     32         // k-chunk
#define NCHUNK (KDIM/CH)  // 16

// ---------------------------------------------------------------------------
// Static device scratch
// ---------------------------------------------------------------------------
__device__ __align__(16) float  g_xg[(size_t)M_ * G_];      // interleaved gate pre-acts
__device__ __align__(16) __half gX_hi[(size_t)M_ * KDIM];   // X in plain fp16 (2-term xg split)
__device__ __align__(16) __half gWih_hi[(size_t)G_ * KDIM]; // interleaved rows
__device__ __align__(16) __half gWih_lo[(size_t)G_ * KDIM];
__device__ __align__(16) __half gWhh_hi[(size_t)G_ * KDIM]; // interleaved rows
__device__ __align__(16) __half gWhh_lo[(size_t)G_ * KDIM];
__device__ float g_biasI[G_];                               // interleaved bih+bhh
__device__ __align__(16) __half g_h_hi[2][(size_t)N_ * H_];
__device__ __align__(16) __half g_h_lo[2][(size_t)N_ * H_];
__device__ float g_c[(size_t)N_ * H_];

// ---------------------------------------------------------------------------
// PTX helpers
// ---------------------------------------------------------------------------
__device__ __forceinline__ uint32_t smem_u32_of(const void* p) {
    uint32_t a;
    asm("{ .reg .u64 t; cvta.to.shared.u64 t, %1; cvt.u32.u64 %0, t; }" : "=r"(a) : "l"(p));
    return a;
}
__device__ __forceinline__ void cp16(uint32_t dst, const void* src) {
    asm volatile("cp.async.cg.shared.global [%0], [%1], 16;" :: "r"(dst), "l"(src));
}
__device__ __forceinline__ void cp_commit() {
    asm volatile("cp.async.commit_group;" ::: "memory");
}
template<int NN> __device__ __forceinline__ void cp_wait() {
    asm volatile("cp.async.wait_group %0;" :: "n"(NN) : "memory");
}
__device__ __forceinline__ void ldm4(uint32_t addr, uint32_t* r) {
    asm volatile("ldmatrix.sync.aligned.m8n8.x4.shared.b16 {%0,%1,%2,%3}, [%4];"
        : "=r"(r[0]), "=r"(r[1]), "=r"(r[2]), "=r"(r[3]) : "r"(addr));
}
__device__ __forceinline__ void mma16816(float* c, const uint32_t* a, const uint32_t* b) {
    asm volatile("mma.sync.aligned.m16n8k16.row.col.f32.f16.f16.f32 "
        "{%0,%1,%2,%3}, {%4,%5,%6,%7}, {%8,%9}, {%0,%1,%2,%3};"
        : "+f"(c[0]), "+f"(c[1]), "+f"(c[2]), "+f"(c[3])
        : "r"(a[0]), "r"(a[1]), "r"(a[2]), "r"(a[3]), "r"(b[0]), "r"(b[1]));
}
__device__ __forceinline__ void f2split(float x, __half& hi, __half& lo) {
    hi = __float2half_rn(x);
    lo = __float2half_rn(x - __half2float(hi));
}

// ---------------------------------------------------------------------------
// Setup kernels
// ---------------------------------------------------------------------------
__global__ void init_state_kernel() {
    int idx = blockIdx.x * blockDim.x + threadIdx.x;
    if (idx < N_ * H_) {
        g_h_hi[0][idx] = __float2half_rn(0.0f);
        g_h_lo[0][idx] = __float2half_rn(0.0f);
        g_c[idx] = 0.0f;
    }
}

__global__ void conv_x_kernel(const float* __restrict__ X) {
    size_t base = ((size_t)blockIdx.x * blockDim.x + threadIdx.x) * 4;
    if (base < (size_t)M_ * KDIM) {
        float4 v = *(const float4*)(X + base);
        __half2 p0 = make_half2(__float2half_rn(v.x), __float2half_rn(v.y));
        __half2 p1 = make_half2(__float2half_rn(v.z), __float2half_rn(v.w));
        *(__half2*)(gX_hi + base)     = p0;
        *(__half2*)(gX_hi + base + 2) = p1;
    }
}

__global__ void conv_w_kernel(const float* __restrict__ Wih,
                              const float* __restrict__ Whh,
                              const float* __restrict__ bih,
                              const float* __restrict__ bhh) {
    int jp = blockIdx.x;                 // interleaved dst row 0..2047
    int gate = jp & 3, h = jp >> 2;
    int j = gate * H_ + h;               // source row
    const float* si = Wih + (size_t)j * KDIM;
    const float* sh = Whh + (size_t)j * KDIM;
    for (int k = threadIdx.x; k < KDIM; k += blockDim.x) {
        __half hi, lo;
        f2split(si[k], hi, lo);
        gWih_hi[(size_t)jp * KDIM + k] = hi; gWih_lo[(size_t)jp * KDIM + k] = lo;
        f2split(sh[k], hi, lo);
        gWhh_hi[(size_t)jp * KDIM + k] = hi; gWhh_lo[(size_t)jp * KDIM + k] = lo;
    }
    if (threadIdx.x == 0) g_biasI[jp] = bih[j] + bhh[j];
}

// ---------------------------------------------------------------------------
// x_gates GEMM: 128x128 tile, grid (16, 500), 3-stage, 2 CTAs/SM (as R11/R12).
// A = X plain fp16; B = W_ih hi+lo. D = A*Bh + A*Bl (2-term split).
// ---------------------------------------------------------------------------
#define XG_STAGE 30720
#define XG_SMEM  (XG_STAGE * 3)    // 92160

__global__ __launch_bounds__(256, 2)
void xg_mma_kernel() {
    extern __shared__ char smem[];
    const uint32_t sb = smem_u32_of(smem);
    __shared__ float bias_s[128];
    const int tid = threadIdx.x;
    const int j0 = blockIdx.x * 128;
    const int m0 = blockIdx.y * 128;
    if (tid < 128) bias_s[tid] = g_biasI[j0 + tid];

    const __half* Ah = gX_hi   + (size_t)m0 * KDIM;
    const __half* Bh = gWih_hi + (size_t)j0 * KDIM;
    const __half* Bl = gWih_lo + (size_t)j0 * KDIM;

    const int lane = tid & 31, wid = tid >> 5;
    const int mw = (wid & 1) * 64, nw = (wid >> 1) * 32;
    const int a_row = mw + (lane & 15);
    const int a_col = (lane >> 4) * 8;
    const int b_row = nw + ((lane >> 4) << 3) + (lane & 7);
    const int b_col = ((lane >> 3) & 1) * 8;

    float acc[4][4][4];
    #pragma unroll
    for (int a = 0; a < 4; ++a)
        #pragma unroll
        for (int b = 0; b < 4; ++b)
            #pragma unroll
            for (int d = 0; d < 4; ++d) acc[a][b][d] = 0.0f;

    #define XLOAD(stg, kc) do {                                          \
        uint32_t _b = sb + (uint32_t)(stg) * XG_STAGE;                   \
        _Pragma("unroll")                                                \
        for (int u = tid; u < 512; u += 256) {                           \
            int r_ = u >> 2, cg_ = (u & 3) * 8;                          \
            cp16(_b + (uint32_t)(r_ * LDS_ + cg_) * 2,                   \
                 Ah + (size_t)r_ * KDIM + (kc) + cg_);                   \
        }                                                                \
        _Pragma("unroll")                                                \
        for (int u = tid; u < 512; u += 256) {                           \
            int r_ = u >> 2, cg_ = (u & 3) * 8;                          \
            uint32_t d_ = _b + 10240 + (uint32_t)(r_ * LDS_ + cg_) * 2;  \
            size_t g_ = (size_t)r_ * KDIM + (kc) + cg_;                  \
            cp16(d_,         Bh + g_);                                   \
            cp16(d_ + 10240, Bl + g_);                                   \
        }                                                                \
    } while (0)

    XLOAD(0, 0);      cp_commit();
    XLOAD(1, CH);     cp_commit();

    #pragma unroll 1
    for (int c = 0; c < NCHUNK; ++c) {
        cp_wait<1>();
        __syncthreads();
        if (c + 2 < NCHUNK) XLOAD((c + 2) % 3, (c + 2) * CH);
        cp_commit();

        const uint32_t base = sb + (uint32_t)(c % 3) * XG_STAGE;
        #pragma unroll
        for (int kk = 0; kk < CH; kk += 16) {
            uint32_t ra[4][4], rbh[2][4], rbl[2][4];
            #pragma unroll
            for (int mi = 0; mi < 4; ++mi) {
                uint32_t aa = base + (uint32_t)((a_row + mi * 16) * LDS_ + kk + a_col) * 2;
                ldm4(aa, ra[mi]);
            }
            #pragma unroll
            for (int nj = 0; nj < 2; ++nj) {
                uint32_t ba = base + 10240 + (uint32_t)((b_row + nj * 16) * LDS_ + kk + b_col) * 2;
                ldm4(ba, rbh[nj]);
                ldm4(ba + 10240, rbl[nj]);
            }
            #pragma unroll
            for (int mi = 0; mi < 4; ++mi) {
                #pragma unroll
                for (int b8 = 0; b8 < 4; ++b8) {
                    const uint32_t* bh = &rbh[b8 >> 1][(b8 & 1) * 2];
                    const uint32_t* bl = &rbl[b8 >> 1][(b8 & 1) * 2];
                    mma16816(acc[mi][b8], ra[mi], bh);   // a*hi
                    mma16816(acc[mi][b8], ra[mi], bl);   // a*lo
                }
            }
        }
    }
    #undef XLOAD

    #pragma unroll
    for (int mi = 0; mi < 4; ++mi) {
        #pragma unroll
        for (int h2 = 0; h2 < 2; ++h2) {
            const int r = m0 + mw + mi * 16 + (lane >> 2) + h2 * 8;
            float* dst = g_xg + (size_t)r * G_ + j0;
            #pragma unroll
            for (int ni = 0; ni < 4; ++ni) {
                const int cc = nw + ni * 8 + (lane & 3) * 2;
                float2 v = make_float2(acc[mi][ni][h2 * 2 + 0] + bias_s[cc],
                                       acc[mi][ni][h2 * 2 + 1] + bias_s[cc + 1]);
                *(float2*)(dst + cc) = v;
            }
        }
    }
}

// ---------------------------------------------------------------------------
// Step kernel: 128x128 tile (128 rows x 32 h-cols x 4 gates), grid (16,5) =
// 80 CTAs, BUT with 512 threads (16 warps) per CTA so each SM keeps 16 warps
// of latency-hiding (R13's failure was 8 warps/SM, not the tiling).
// Warp grid 4m x 4n: warp tile 32 rows x 32 gate-cols (MI=2, 2 n16-frags).
// 3-term split; CH=32, 3-stage pipeline; xg tile prefetched in stage-1 group.
// Stage (elems): Hhi[128*40] Hlo[128*40] Whi[128*40] Wlo[128*40] = 40960 B
// smem: [0 .. 3*40960) stages (reused for C staging); [122880 ..) xg tile.
// ---------------------------------------------------------------------------
#define SP_STAGE  40960
#define SP_XGOFF  (3 * SP_STAGE)            // 122880
#define STEP_SMEM (SP_XGOFF + 128*128*4)    // 188416

__global__ __launch_bounds__(512, 1)
void step_mma_kernel(float* __restrict__ out, int t) {
    extern __shared__ char smem[];
    const uint32_t sb = smem_u32_of(smem);
    const int tid = threadIdx.x;
    const int jb = blockIdx.x;           // 0..15
    const int j0 = jb * 128;             // interleaved gate-col base
    const int hb = jb * 32;              // h-col base
    const int n0 = blockIdx.y * 128;     // row base
    const int lane = tid & 31, wid = tid >> 5;
    const int wm = wid & 3, wn = wid >> 2;   // 4m x 4n warp grid

    const int cur = t & 1, nxt = cur ^ 1;
    const __half* Hh = g_h_hi[cur] + (size_t)n0 * H_;
    const __half* Hl = g_h_lo[cur] + (size_t)n0 * H_;
    const __half* Wh = gWhh_hi + (size_t)j0 * KDIM;
    const __half* Wl = gWhh_lo + (size_t)j0 * KDIM;

    const int a_row = wm * 32 + (lane & 15);
    const int a_col = (lane >> 4) * 8;
    const int b_row = wn * 32 + ((lane >> 4) << 3) + (lane & 7);
    const int b_col = ((lane >> 3) & 1) * 8;

    float acc[2][4][4];
    #pragma unroll
    for (int a = 0; a < 2; ++a)
        #pragma unroll
        for (int b = 0; b < 4; ++b)
            #pragma unroll
            for (int d = 0; d < 4; ++d) acc[a][b][d] = 0.0f;

    // chunk loader: 128 rows h (hi+lo) + 128 rows W (hi+lo), 32 k each.
    // 512 threads -> one cp16 quad per thread.
    #define SLOAD(stg, kc) do {                                              \
        uint32_t _b = sb + (uint32_t)(stg) * SP_STAGE;                       \
        _Pragma("unroll")                                                    \
        for (int u = tid; u < 512; u += 512) {                               \
            int r_ = u >> 2, cg_ = (u & 3) * 8;                              \
            uint32_t d_ = _b + (uint32_t)(r_ * LDS_ + cg_) * 2;              \
            size_t gh_ = (size_t)r_ * H_ + (kc) + cg_;                       \
            size_t gw_ = (size_t)r_ * KDIM + (kc) + cg_;                     \
            cp16(d_,         Hh + gh_);                                      \
            cp16(d_ + 10240, Hl + gh_);                                      \
            cp16(d_ + 20480, Wh + gw_);                                      \
            cp16(d_ + 30720, Wl + gw_);                                      \
        }                                                                    \
    } while (0)

    // G0: stage 0.  G1: stage 1 + the xg tile (gates chunk 1, not chunk 0).
    SLOAD(0, 0);
    cp_commit();
    SLOAD(1, CH);
    #pragma unroll
    for (int u = tid; u < 128 * 32; u += 512) {
        int r = u >> 5, cg = (u & 31) * 4;
        cp16(sb + SP_XGOFF + (uint32_t)(r * 128 + cg) * 4,
             g_xg + ((size_t)(n0 + r) * T_ + t) * G_ + j0 + cg);
    }
    cp_commit();

    #pragma unroll 1
    for (int c = 0; c < NCHUNK; ++c) {
        cp_wait<1>();             // chunk c complete (in-order group retire)
        __syncthreads();          // all warps done with the buffer being refilled
        if (c + 2 < NCHUNK) SLOAD((c + 2) % 3, (c + 2) * CH);
        cp_commit();              // uniform accounting (possibly empty)

        const uint32_t base = sb + (uint32_t)(c % 3) * SP_STAGE;
        #pragma unroll
        for (int kk = 0; kk < CH; kk += 16) {
            uint32_t ra[2][4], rl[2][4], rbh[2][4], rbl[2][4];
            #pragma unroll
            for (int mi = 0; mi < 2; ++mi) {
                uint32_t aa = base + (uint32_t)((a_row + mi * 16) * LDS_ + kk + a_col) * 2;
                ldm4(aa, ra[mi]);
                ldm4(aa + 10240, rl[mi]);
            }
            #pragma unroll
            for (int nj = 0; nj < 2; ++nj) {
                uint32_t ba = base + 20480 + (uint32_t)((b_row + nj * 16) * LDS_ + kk + b_col) * 2;
                ldm4(ba, rbh[nj]);
                ldm4(ba + 10240, rbl[nj]);
            }
            #pragma unroll
            for (int mi = 0; mi < 2; ++mi) {
                #pragma unroll
                for (int b8 = 0; b8 < 4; ++b8) {
                    const uint32_t* bhp = &rbh[b8 >> 1][(b8 & 1) * 2];
                    const uint32_t* blp = &rbl[b8 >> 1][(b8 & 1) * 2];
                    mma16816(acc[mi][b8], ra[mi], bhp);   // hi*hi
                    mma16816(acc[mi][b8], ra[mi], blp);   // hi*lo
                    mma16816(acc[mi][b8], rl[mi], bhp);   // lo*hi
                }
            }
        }
    }
    #undef SLOAD

    // all warps done reading stage buffers before C staging reuses them
    __syncthreads();

    // stage C tile [128][132] fp32 in the stage region (xg tile untouched)
    float* Cs = (float*)smem;
    #pragma unroll
    for (int mi = 0; mi < 2; ++mi) {
        #pragma unroll
        for (int b8 = 0; b8 < 4; ++b8) {
            const int r = wm * 32 + mi * 16 + (lane >> 2);
            const int cc = wn * 32 + b8 * 8 + (lane & 3) * 2;
            *(float2*)&Cs[r * 132 + cc]       = make_float2(acc[mi][b8][0], acc[mi][b8][1]);
            *(float2*)&Cs[(r + 8) * 132 + cc] = make_float2(acc[mi][b8][2], acc[mi][b8][3]);
        }
    }
    __syncthreads();

    // fused LSTM cell update: 8 cells/thread (128 rows x 32 h-cols, 512 thr)
    const float* xgS = (const float*)(smem + SP_XGOFF);
    const bool last = (t == T_ - 1);
    const int hl = tid & 31;             // h lane 0..31
    const int rg = tid >> 5;             // row group 0..15
    #pragma unroll
    for (int e = 0; e < 8; ++e) {
        const int r = rg + e * 16;
        const int gn = n0 + r;
        float4 cg = *(const float4*)&Cs[r * 132 + hl * 4];
        float4 xv = *(const float4*)&xgS[r * 128 + hl * 4];
        float ig = cg.x + xv.x, fg = cg.y + xv.y;
        float gg = cg.z + xv.z, og = cg.w + xv.w;

        float is = 1.0f / (1.0f + __expf(-ig));
        float fs = 1.0f / (1.0f + __expf(-fg));
        float gt = tanhf(gg);
        float os = 1.0f / (1.0f + __expf(-og));

        const size_t ci = (size_t)gn * H_ + hb + hl;
        float c = fs * g_c[ci] + is * gt;
        g_c[ci] = c;
        float hv = os * tanhf(c);
        if (last) {
            out[ci] = hv;
        } else {
            __half hi, lo;
            f2split(hv, hi, lo);
            g_h_hi[nxt][ci] = hi;
            g_h_lo[nxt][ci] = lo;
        }
    }
}

// ---------------------------------------------------------------------------
// Launch
// ---------------------------------------------------------------------------
extern "C" void kernel_launch(void* const* d_in, const int* in_sizes, int n_in,
                              void* d_out, int out_size)
{
    const float* X   = (const float*)d_in[0];   // [B,Q,T,D] == [N*T, D]
    const float* Wih = (const float*)d_in[1];   // [4H, D]
    const float* Whh = (const float*)d_in[2];   // [4H, H]
    const float* bih = (const float*)d_in[3];   // [4H]
    const float* bhh = (const float*)d_in[4];   // [4H]
    float* out = (float*)d_out;                 // [B,Q,H] == [N, H]

    cudaFuncSetAttribute(xg_mma_kernel,   cudaFuncAttributeMaxDynamicSharedMemorySize, XG_SMEM);
    cudaFuncSetAttribute(step_mma_kernel, cudaFuncAttributeMaxDynamicSharedMemorySize, STEP_SMEM);

    init_state_kernel<<<(N_ * H_ + 255) / 256, 256>>>();
    conv_x_kernel<<<(int)(((size_t)M_ * KDIM / 4 + 255) / 256), 256>>>(X);
    conv_w_kernel<<<G_, 256>>>(Wih, Whh, bih, bhh);

    xg_mma_kernel<<<dim3(G_ / 128, M_ / 128), 256, XG_SMEM>>>();

    for (int t = 0; t < T_; ++t) {
        step_mma_kernel<<<dim3(16, 5), 512, STEP_SMEM>>>(out, t);
    }
}

// round 15
// speedup vs baseline: 1.6106x; 1.4907x over previous
#include <cuda_runtime.h>
#include <cuda_fp16.h>
#include <stdint.h>
#include <math.h>

// Problem constants
#define B_   32
#define Q_   20
#define T_   100
#define KDIM 512          // D == H == 512 (GEMM K dim)
#define H_   512
#define N_   (B_*Q_)      // 640 sequences
#define G_   (4*H_)       // 2048 gate columns (interleaved: jp = h*4 + gate)
#define M_   (N_*T_)      // 64000 rows of the x_gates GEMM

#define LDS_   40         // smem row stride (fp16 elems) for 32-wide k-chunks
#define CH     32         // k-chunk
#define NCHUNK (KDIM/CH)  // 16

// ---------------------------------------------------------------------------
// Static device scratch
// ---------------------------------------------------------------------------
__device__ __align__(16) float  g_xg[(size_t)M_ * G_];      // interleaved gate pre-acts
__device__ __align__(16) __half gX_hi[(size_t)M_ * KDIM];   // X in plain fp16 (2-term xg split)
__device__ __align__(16) __half gWih_hi[(size_t)G_ * KDIM]; // interleaved rows
__device__ __align__(16) __half gWih_lo[(size_t)G_ * KDIM];
__device__ __align__(16) __half gWhh_hi[(size_t)G_ * KDIM]; // interleaved rows
__device__ float g_biasI[G_];                               // interleaved bih+bhh
__device__ __align__(16) __half g_h_hi[2][(size_t)N_ * H_];
__device__ __align__(16) __half g_h_lo[2][(size_t)N_ * H_];
__device__ float g_c[(size_t)N_ * H_];

// ---------------------------------------------------------------------------
// PTX helpers
// ---------------------------------------------------------------------------
__device__ __forceinline__ uint32_t smem_u32_of(const void* p) {
    uint32_t a;
    asm("{ .reg .u64 t; cvta.to.shared.u64 t, %1; cvt.u32.u64 %0, t; }" : "=r"(a) : "l"(p));
    return a;
}
__device__ __forceinline__ void cp16(uint32_t dst, const void* src) {
    asm volatile("cp.async.cg.shared.global [%0], [%1], 16;" :: "r"(dst), "l"(src));
}
__device__ __forceinline__ void cp_commit() {
    asm volatile("cp.async.commit_group;" ::: "memory");
}
template<int NN> __device__ __forceinline__ void cp_wait() {
    asm volatile("cp.async.wait_group %0;" :: "n"(NN) : "memory");
}
__device__ __forceinline__ void ldm4(uint32_t addr, uint32_t* r) {
    asm volatile("ldmatrix.sync.aligned.m8n8.x4.shared.b16 {%0,%1,%2,%3}, [%4];"
        : "=r"(r[0]), "=r"(r[1]), "=r"(r[2]), "=r"(r[3]) : "r"(addr));
}
__device__ __forceinline__ void mma16816(float* c, const uint32_t* a, const uint32_t* b) {
    asm volatile("mma.sync.aligned.m16n8k16.row.col.f32.f16.f16.f32 "
        "{%0,%1,%2,%3}, {%4,%5,%6,%7}, {%8,%9}, {%0,%1,%2,%3};"
        : "+f"(c[0]), "+f"(c[1]), "+f"(c[2]), "+f"(c[3])
        : "r"(a[0]), "r"(a[1]), "r"(a[2]), "r"(a[3]), "r"(b[0]), "r"(b[1]));
}
__device__ __forceinline__ void f2split(float x, __half& hi, __half& lo) {
    hi = __float2half_rn(x);
    lo = __float2half_rn(x - __half2float(hi));
}

// ---------------------------------------------------------------------------
// Setup kernels
// ---------------------------------------------------------------------------
__global__ void init_state_kernel() {
    int idx = blockIdx.x * blockDim.x + threadIdx.x;
    if (idx < N_ * H_) {
        g_h_hi[0][idx] = __float2half_rn(0.0f);
        g_h_lo[0][idx] = __float2half_rn(0.0f);
        g_c[idx] = 0.0f;
    }
}

__global__ void conv_x_kernel(const float* __restrict__ X) {
    size_t base = ((size_t)blockIdx.x * blockDim.x + threadIdx.x) * 4;
    if (base < (size_t)M_ * KDIM) {
        float4 v = *(const float4*)(X + base);
        __half2 p0 = make_half2(__float2half_rn(v.x), __float2half_rn(v.y));
        __half2 p1 = make_half2(__float2half_rn(v.z), __float2half_rn(v.w));
        *(__half2*)(gX_hi + base)     = p0;
        *(__half2*)(gX_hi + base + 2) = p1;
    }
}

__global__ void conv_w_kernel(const float* __restrict__ Wih,
                              const float* __restrict__ Whh,
                              const float* __restrict__ bih,
                              const float* __restrict__ bhh) {
    int jp = blockIdx.x;                 // interleaved dst row 0..2047
    int gate = jp & 3, h = jp >> 2;
    int j = gate * H_ + h;               // source row
    const float* si = Wih + (size_t)j * KDIM;
    const float* sh = Whh + (size_t)j * KDIM;
    for (int k = threadIdx.x; k < KDIM; k += blockDim.x) {
        __half hi, lo;
        f2split(si[k], hi, lo);
        gWih_hi[(size_t)jp * KDIM + k] = hi; gWih_lo[(size_t)jp * KDIM + k] = lo;
        gWhh_hi[(size_t)jp * KDIM + k] = __float2half_rn(sh[k]);
    }
    if (threadIdx.x == 0) g_biasI[jp] = bih[j] + bhh[j];
}

// ---------------------------------------------------------------------------
// x_gates GEMM: 128x128 tile, grid (16, 500), 3-stage, 2 CTAs/SM (as R11/R12).
// A = X plain fp16; B = W_ih hi+lo. D = A*Bh + A*Bl (2-term split).
// ---------------------------------------------------------------------------
#define XG_STAGE 30720
#define XG_SMEM  (XG_STAGE * 3)    // 92160

__global__ __launch_bounds__(256, 2)
void xg_mma_kernel() {
    extern __shared__ char smem[];
    const uint32_t sb = smem_u32_of(smem);
    __shared__ float bias_s[128];
    const int tid = threadIdx.x;
    const int j0 = blockIdx.x * 128;
    const int m0 = blockIdx.y * 128;
    if (tid < 128) bias_s[tid] = g_biasI[j0 + tid];

    const __half* Ah = gX_hi   + (size_t)m0 * KDIM;
    const __half* Bh = gWih_hi + (size_t)j0 * KDIM;
    const __half* Bl = gWih_lo + (size_t)j0 * KDIM;

    const int lane = tid & 31, wid = tid >> 5;
    const int mw = (wid & 1) * 64, nw = (wid >> 1) * 32;
    const int a_row = mw + (lane & 15);
    const int a_col = (lane >> 4) * 8;
    const int b_row = nw + ((lane >> 4) << 3) + (lane & 7);
    const int b_col = ((lane >> 3) & 1) * 8;

    float acc[4][4][4];
    #pragma unroll
    for (int a = 0; a < 4; ++a)
        #pragma unroll
        for (int b = 0; b < 4; ++b)
            #pragma unroll
            for (int d = 0; d < 4; ++d) acc[a][b][d] = 0.0f;

    #define XLOAD(stg, kc) do {                                          \
        uint32_t _b = sb + (uint32_t)(stg) * XG_STAGE;                   \
        _Pragma("unroll")                                                \
        for (int u = tid; u < 512; u += 256) {                           \
            int r_ = u >> 2, cg_ = (u & 3) * 8;                          \
            cp16(_b + (uint32_t)(r_ * LDS_ + cg_) * 2,                   \
                 Ah + (size_t)r_ * KDIM + (kc) + cg_);                   \
        }                                                                \
        _Pragma("unroll")                                                \
        for (int u = tid; u < 512; u += 256) {                           \
            int r_ = u >> 2, cg_ = (u & 3) * 8;                          \
            uint32_t d_ = _b + 10240 + (uint32_t)(r_ * LDS_ + cg_) * 2;  \
            size_t g_ = (size_t)r_ * KDIM + (kc) + cg_;                  \
            cp16(d_,         Bh + g_);                                   \
            cp16(d_ + 10240, Bl + g_);                                   \
        }                                                                \
    } while (0)

    XLOAD(0, 0);      cp_commit();
    XLOAD(1, CH);     cp_commit();

    #pragma unroll 1
    for (int c = 0; c < NCHUNK; ++c) {
        cp_wait<1>();
        __syncthreads();
        if (c + 2 < NCHUNK) XLOAD((c + 2) % 3, (c + 2) * CH);
        cp_commit();

        const uint32_t base = sb + (uint32_t)(c % 3) * XG_STAGE;
        #pragma unroll
        for (int kk = 0; kk < CH; kk += 16) {
            uint32_t ra[4][4], rbh[2][4], rbl[2][4];
            #pragma unroll
            for (int mi = 0; mi < 4; ++mi) {
                uint32_t aa = base + (uint32_t)((a_row + mi * 16) * LDS_ + kk + a_col) * 2;
                ldm4(aa, ra[mi]);
            }
            #pragma unroll
            for (int nj = 0; nj < 2; ++nj) {
                uint32_t ba = base + 10240 + (uint32_t)((b_row + nj * 16) * LDS_ + kk + b_col) * 2;
                ldm4(ba, rbh[nj]);
                ldm4(ba + 10240, rbl[nj]);
            }
            #pragma unroll
            for (int mi = 0; mi < 4; ++mi) {
                #pragma unroll
                for (int b8 = 0; b8 < 4; ++b8) {
                    const uint32_t* bh = &rbh[b8 >> 1][(b8 & 1) * 2];
                    const uint32_t* bl = &rbl[b8 >> 1][(b8 & 1) * 2];
                    mma16816(acc[mi][b8], ra[mi], bh);   // a*hi
                    mma16816(acc[mi][b8], ra[mi], bl);   // a*lo
                }
            }
        }
    }
    #undef XLOAD

    #pragma unroll
    for (int mi = 0; mi < 4; ++mi) {
        #pragma unroll
        for (int h2 = 0; h2 < 2; ++h2) {
            const int r = m0 + mw + mi * 16 + (lane >> 2) + h2 * 8;
            float* dst = g_xg + (size_t)r * G_ + j0;
            #pragma unroll
            for (int ni = 0; ni < 4; ++ni) {
                const int cc = nw + ni * 8 + (lane & 3) * 2;
                float2 v = make_float2(acc[mi][ni][h2 * 2 + 0] + bias_s[cc],
                                       acc[mi][ni][h2 * 2 + 1] + bias_s[cc + 1]);
                *(float2*)(dst + cc) = v;
            }
        }
    }
}

// ---------------------------------------------------------------------------
// Step kernel body, templated on row count MT (96 or 64). R12 structure, but
// 2-term recurrent split: h_hi*W_hi + h_lo*W_hi (W_lo dropped — W quantization
// error is the smallest of the 3 terms; h_lo correction kept since h errors
// compound). W_lo never loaded -> per-step W traffic halves, MMA work -33%.
// CH=32, 3-stage pipeline + xg tile prefetched to smem (in stage-0's group).
// Stage (elems): Hhi[MT*40] Hlo[MT*40] Whi[64*40]
// smem map: [0 .. 3*STAGE_B)  pipeline stages (stage 0 reused for C staging)
//           [3*STAGE_B .. +MT*64*4)  xg tile [MT][64] fp32
// ---------------------------------------------------------------------------
#define STEP_SMEM (3 * ((2*96*LDS_ + 64*LDS_) * 2) + 96*64*4)   // 86016

template<int MT>
__device__ __forceinline__ void step_body(
    char* smem, uint32_t sb, int tid, int j0, int hb, int n0, int t,
    float* __restrict__ out)
{
    const int MI = MT / 32;
    const int STAGE_E = 2 * MT * LDS_ + 64 * LDS_;       // elems per stage
    const int STAGE_B = STAGE_E * 2;                     // bytes
    const int XGOFF   = 3 * STAGE_B;                     // xg tile offset (bytes)
    const int lane = tid & 31, wid = tid >> 5;
    const int wm = wid & 1, wn = wid >> 1;

    const int cur = t & 1, nxt = cur ^ 1;
    const __half* Hh = g_h_hi[cur] + (size_t)n0 * H_;
    const __half* Hl = g_h_lo[cur] + (size_t)n0 * H_;
    const __half* Wh = gWhh_hi + (size_t)j0 * KDIM;

    const int a_row = wm * (MI * 16) + (lane & 15);
    const int a_col = (lane >> 4) * 8;
    const int b_row = wn * 16 + ((lane >> 4) << 3) + (lane & 7);
    const int b_col = ((lane >> 3) & 1) * 8;

    float acc[MI > 2 ? 3 : 2][2][4];
    #pragma unroll
    for (int a = 0; a < MI; ++a)
        #pragma unroll
        for (int b = 0; b < 2; ++b)
            #pragma unroll
            for (int d = 0; d < 4; ++d) acc[a][b][d] = 0.0f;

    // chunk loader: MT rows h (hi+lo) + 64 rows W (hi only), 32 k each
    #define SLOAD(stg, kc) do {                                              \
        uint32_t _b = sb + (uint32_t)(stg) * STAGE_B;                        \
        _Pragma("unroll")                                                    \
        for (int u = tid; u < MT * 4; u += 256) {                            \
            int r_ = u >> 2, cg_ = (u & 3) * 8;                              \
            uint32_t d_ = _b + (uint32_t)(r_ * LDS_ + cg_) * 2;              \
            size_t g_ = (size_t)r_ * H_ + (kc) + cg_;                        \
            cp16(d_,                 Hh + g_);                               \
            cp16(d_ + MT * LDS_ * 2, Hl + g_);                               \
        }                                                                    \
        _Pragma("unroll")                                                    \
        for (int u = tid; u < 256; u += 256) {                               \
            int r_ = u >> 2, cg_ = (u & 3) * 8;                              \
            uint32_t d_ = _b + (uint32_t)(2 * MT * LDS_ + r_ * LDS_ + cg_) * 2; \
            cp16(d_, Wh + (size_t)r_ * KDIM + (kc) + cg_);                   \
        }                                                                    \
    } while (0)

    // group G0: stage 0 + the whole xg tile for this (tile, t)
    SLOAD(0, 0);
    #pragma unroll
    for (int u = tid; u < MT * 16; u += 256) {
        int r = u >> 4, cg = (u & 15) * 4;
        cp16(sb + XGOFF + (uint32_t)(r * 64 + cg) * 4,
             g_xg + ((size_t)(n0 + r) * T_ + t) * G_ + j0 + cg);
    }
    cp_commit();
    // group G1: stage 1
    SLOAD(1, CH);
    cp_commit();

    #pragma unroll 1
    for (int c = 0; c < NCHUNK; ++c) {
        cp_wait<1>();             // stage c (+xg if c==0) complete
        __syncthreads();          // all warps done with the buffer being refilled
        if (c + 2 < NCHUNK) SLOAD((c + 2) % 3, (c + 2) * CH);
        cp_commit();              // uniform accounting

        const uint32_t base = sb + (uint32_t)(c % 3) * STAGE_B;
        #pragma unroll
        for (int kk = 0; kk < CH; kk += 16) {
            uint32_t ra[MI > 2 ? 3 : 2][4], rl[MI > 2 ? 3 : 2][4], rbh[4];
            #pragma unroll
            for (int mi = 0; mi < MI; ++mi) {
                uint32_t aa = base + (uint32_t)((a_row + mi * 16) * LDS_ + kk + a_col) * 2;
                ldm4(aa, ra[mi]);
                ldm4(aa + MT * LDS_ * 2, rl[mi]);
            }
            uint32_t ba = base + (uint32_t)(2 * MT * LDS_ + b_row * LDS_ + kk + b_col) * 2;
            ldm4(ba, rbh);
            #pragma unroll
            for (int mi = 0; mi < MI; ++mi) {
                #pragma unroll
                for (int b8 = 0; b8 < 2; ++b8) {
                    const uint32_t* bhp = &rbh[b8 * 2];
                    mma16816(acc[mi][b8], ra[mi], bhp);   // hi*hi
                    mma16816(acc[mi][b8], rl[mi], bhp);   // lo*hi
                }
            }
        }
    }
    #undef SLOAD

    // all warps done reading stage buffers before C staging reuses stage 0
    __syncthreads();

    // stage C tile [MT][68] in smem (stage-0/1 region; xg tile untouched)
    float* Cs = (float*)smem;
    #pragma unroll
    for (int mi = 0; mi < MI; ++mi) {
        #pragma unroll
        for (int b8 = 0; b8 < 2; ++b8) {
            const int r = wm * (MI * 16) + mi * 16 + (lane >> 2);
            const int cc = wn * 16 + b8 * 8 + (lane & 3) * 2;
            *(float2*)&Cs[r * 68 + cc]       = make_float2(acc[mi][b8][0], acc[mi][b8][1]);
            *(float2*)&Cs[(r + 8) * 68 + cc] = make_float2(acc[mi][b8][2], acc[mi][b8][3]);
        }
    }
    __syncthreads();

    // fused LSTM cell update: MT/16 cells per thread; xg from smem
    const float* xgS = (const float*)(smem + XGOFF);
    const bool last = (t == T_ - 1);
    const int hl = tid & 15;
    const int rg = tid >> 4;
    #pragma unroll
    for (int e = 0; e < MT / 16; ++e) {
        const int r = rg + e * 16;
        const int gn = n0 + r;
        float4 cg = *(const float4*)&Cs[r * 68 + hl * 4];
        float4 xv = *(const float4*)&xgS[r * 64 + hl * 4];
        float ig = cg.x + xv.x, fg = cg.y + xv.y;
        float gg = cg.z + xv.z, og = cg.w + xv.w;

        float is = 1.0f / (1.0f + __expf(-ig));
        float fs = 1.0f / (1.0f + __expf(-fg));
        float gt = tanhf(gg);
        float os = 1.0f / (1.0f + __expf(-og));

        const size_t ci = (size_t)gn * H_ + hb + hl;
        float c = fs * g_c[ci] + is * gt;
        g_c[ci] = c;
        float hv = os * tanhf(c);
        if (last) {
            out[ci] = hv;
        } else {
            __half hi, lo;
            f2split(hv, hi, lo);
            g_h_hi[nxt][ci] = hi;
            g_h_lo[nxt][ci] = lo;
        }
    }
}

// ---------------------------------------------------------------------------
// Step kernel: 288 CTAs = 32 jb x 9 row-tiles (2x96 + 7x64 rows), single wave.
// ---------------------------------------------------------------------------
__global__ __launch_bounds__(256, 2)
void step_mma_kernel(float* __restrict__ out, int t) {
    extern __shared__ char smem[];
    const uint32_t sb = smem_u32_of(smem);
    const int tid = threadIdx.x;
    const int bid = blockIdx.x;
    const int nt = bid >> 5;          // 0..8 (row tile)
    const int jb = bid & 31;          // 0..31 (col block)
    const int j0 = jb * 64;
    const int hb = jb * 16;

    if (nt < 2) {
        step_body<96>(smem, sb, tid, j0, hb, nt * 96, t, out);
    } else {
        step_body<64>(smem, sb, tid, j0, hb, 192 + (nt - 2) * 64, t, out);
    }
}

// ---------------------------------------------------------------------------
// Launch
// ---------------------------------------------------------------------------
extern "C" void kernel_launch(void* const* d_in, const int* in_sizes, int n_in,
                              void* d_out, int out_size)
{
    const float* X   = (const float*)d_in[0];   // [B,Q,T,D] == [N*T, D]
    const float* Wih = (const float*)d_in[1];   // [4H, D]
    const float* Whh = (const float*)d_in[2];   // [4H, H]
    const float* bih = (const float*)d_in[3];   // [4H]
    const float* bhh = (const float*)d_in[4];   // [4H]
    float* out = (float*)d_out;                 // [B,Q,H] == [N, H]

    cudaFuncSetAttribute(xg_mma_kernel,   cudaFuncAttributeMaxDynamicSharedMemorySize, XG_SMEM);
    cudaFuncSetAttribute(step_mma_kernel, cudaFuncAttributeMaxDynamicSharedMemorySize, STEP_SMEM);

    init_state_kernel<<<(N_ * H_ + 255) / 256, 256>>>();
    conv_x_kernel<<<(int)(((size_t)M_ * KDIM / 4 + 255) / 256), 256>>>(X);
    conv_w_kernel<<<G_, 256>>>(Wih, Whh, bih, bhh);

    xg_mma_kernel<<<dim3(G_ / 128, M_ / 128), 256, XG_SMEM>>>();

    for (int t = 0; t < T_; ++t) {
        step_mma_kernel<<<288, 256, STEP_SMEM>>>(out, t);
    }
}

// round 16
// speedup vs baseline: 1.8303x; 1.1364x over previous
#include <cuda_runtime.h>
#include <cuda_fp16.h>
#include <stdint.h>
#include <math.h>

// Problem constants
#define B_   32
#define Q_   20
#define T_   100
#define KDIM 512          // D == H == 512 (GEMM K dim)
#define H_   512
#define N_   (B_*Q_)      // 640 sequences
#define G_   (4*H_)       // 2048 gate columns (interleaved: jp = h*4 + gate)
#define M_   (N_*T_)      // 64000 rows of the x_gates GEMM

#define LDS_   40         // smem row stride (fp16 elems) for 32-wide k-chunks
#define CH     32         // k-chunk
#define NCHUNK (KDIM/CH)  // 16

// ---------------------------------------------------------------------------
// Static device scratch
// ---------------------------------------------------------------------------
__device__ __align__(16) float  g_xg[(size_t)M_ * G_];      // interleaved gate pre-acts
__device__ __align__(16) __half gX_hi[(size_t)M_ * KDIM];   // X in plain fp16
__device__ __align__(16) __half gWih_hi[(size_t)G_ * KDIM]; // interleaved rows, plain fp16
__device__ __align__(16) __half gWhh_hi[(size_t)G_ * KDIM]; // interleaved rows, plain fp16
__device__ float g_biasI[G_];                               // interleaved bih+bhh
__device__ __align__(16) __half g_h_hi[2][(size_t)N_ * H_];
__device__ __align__(16) __half g_h_lo[2][(size_t)N_ * H_];
__device__ float g_c[(size_t)N_ * H_];

// ---------------------------------------------------------------------------
// PTX helpers
// ---------------------------------------------------------------------------
__device__ __forceinline__ uint32_t smem_u32_of(const void* p) {
    uint32_t a;
    asm("{ .reg .u64 t; cvta.to.shared.u64 t, %1; cvt.u32.u64 %0, t; }" : "=r"(a) : "l"(p));
    return a;
}
__device__ __forceinline__ void cp16(uint32_t dst, const void* src) {
    asm volatile("cp.async.cg.shared.global [%0], [%1], 16;" :: "r"(dst), "l"(src));
}
__device__ __forceinline__ void cp_commit() {
    asm volatile("cp.async.commit_group;" ::: "memory");
}
template<int NN> __device__ __forceinline__ void cp_wait() {
    asm volatile("cp.async.wait_group %0;" :: "n"(NN) : "memory");
}
__device__ __forceinline__ void ldm4(uint32_t addr, uint32_t* r) {
    asm volatile("ldmatrix.sync.aligned.m8n8.x4.shared.b16 {%0,%1,%2,%3}, [%4];"
        : "=r"(r[0]), "=r"(r[1]), "=r"(r[2]), "=r"(r[3]) : "r"(addr));
}
__device__ __forceinline__ void mma16816(float* c, const uint32_t* a, const uint32_t* b) {
    asm volatile("mma.sync.aligned.m16n8k16.row.col.f32.f16.f16.f32 "
        "{%0,%1,%2,%3}, {%4,%5,%6,%7}, {%8,%9}, {%0,%1,%2,%3};"
        : "+f"(c[0]), "+f"(c[1]), "+f"(c[2]), "+f"(c[3])
        : "r"(a[0]), "r"(a[1]), "r"(a[2]), "r"(a[3]), "r"(b[0]), "r"(b[1]));
}
__device__ __forceinline__ void f2split(float x, __half& hi, __half& lo) {
    hi = __float2half_rn(x);
    lo = __float2half_rn(x - __half2float(hi));
}

// ---------------------------------------------------------------------------
// Setup kernels
// ---------------------------------------------------------------------------
__global__ void init_state_kernel() {
    int idx = blockIdx.x * blockDim.x + threadIdx.x;
    if (idx < N_ * H_) {
        g_h_hi[0][idx] = __float2half_rn(0.0f);
        g_h_lo[0][idx] = __float2half_rn(0.0f);
        g_c[idx] = 0.0f;
    }
}

__global__ void conv_x_kernel(const float* __restrict__ X) {
    size_t base = ((size_t)blockIdx.x * blockDim.x + threadIdx.x) * 4;
    if (base < (size_t)M_ * KDIM) {
        float4 v = *(const float4*)(X + base);
        __half2 p0 = make_half2(__float2half_rn(v.x), __float2half_rn(v.y));
        __half2 p1 = make_half2(__float2half_rn(v.z), __float2half_rn(v.w));
        *(__half2*)(gX_hi + base)     = p0;
        *(__half2*)(gX_hi + base + 2) = p1;
    }
}

__global__ void conv_w_kernel(const float* __restrict__ Wih,
                              const float* __restrict__ Whh,
                              const float* __restrict__ bih,
                              const float* __restrict__ bhh) {
    int jp = blockIdx.x;                 // interleaved dst row 0..2047
    int gate = jp & 3, h = jp >> 2;
    int j = gate * H_ + h;               // source row
    const float* si = Wih + (size_t)j * KDIM;
    const float* sh = Whh + (size_t)j * KDIM;
    for (int k = threadIdx.x; k < KDIM; k += blockDim.x) {
        gWih_hi[(size_t)jp * KDIM + k] = __float2half_rn(si[k]);
        gWhh_hi[(size_t)jp * KDIM + k] = __float2half_rn(sh[k]);
    }
    if (threadIdx.x == 0) g_biasI[jp] = bih[j] + bhh[j];
}

// ---------------------------------------------------------------------------
// x_gates GEMM: 128x128 tile, grid (16, 500), 3-stage, 2 CTAs/SM.
// A = X plain fp16; B = W_ih plain fp16 (single-term — weight lo-drop
// measured at +1.5% rel_err on the recurrent GEMM, one-shot here).
// Stage (bytes): A[10240] Bh[10240] = 20480.
// ---------------------------------------------------------------------------
#define XG_STAGE 20480
#define XG_SMEM  (XG_STAGE * 3)    // 61440

__global__ __launch_bounds__(256, 2)
void xg_mma_kernel() {
    extern __shared__ char smem[];
    const uint32_t sb = smem_u32_of(smem);
    __shared__ float bias_s[128];
    const int tid = threadIdx.x;
    const int j0 = blockIdx.x * 128;
    const int m0 = blockIdx.y * 128;
    if (tid < 128) bias_s[tid] = g_biasI[j0 + tid];

    const __half* Ah = gX_hi   + (size_t)m0 * KDIM;
    const __half* Bh = gWih_hi + (size_t)j0 * KDIM;

    const int lane = tid & 31, wid = tid >> 5;
    const int mw = (wid & 1) * 64, nw = (wid >> 1) * 32;
    const int a_row = mw + (lane & 15);
    const int a_col = (lane >> 4) * 8;
    const int b_row = nw + ((lane >> 4) << 3) + (lane & 7);
    const int b_col = ((lane >> 3) & 1) * 8;

    float acc[4][4][4];
    #pragma unroll
    for (int a = 0; a < 4; ++a)
        #pragma unroll
        for (int b = 0; b < 4; ++b)
            #pragma unroll
            for (int d = 0; d < 4; ++d) acc[a][b][d] = 0.0f;

    #define XLOAD(stg, kc) do {                                          \
        uint32_t _b = sb + (uint32_t)(stg) * XG_STAGE;                   \
        _Pragma("unroll")                                                \
        for (int u = tid; u < 512; u += 256) {                           \
            int r_ = u >> 2, cg_ = (u & 3) * 8;                          \
            cp16(_b + (uint32_t)(r_ * LDS_ + cg_) * 2,                   \
                 Ah + (size_t)r_ * KDIM + (kc) + cg_);                   \
            cp16(_b + 10240 + (uint32_t)(r_ * LDS_ + cg_) * 2,           \
                 Bh + (size_t)r_ * KDIM + (kc) + cg_);                   \
        }                                                                \
    } while (0)

    XLOAD(0, 0);      cp_commit();
    XLOAD(1, CH);     cp_commit();

    #pragma unroll 1
    for (int c = 0; c < NCHUNK; ++c) {
        cp_wait<1>();
        __syncthreads();
        if (c + 2 < NCHUNK) XLOAD((c + 2) % 3, (c + 2) * CH);
        cp_commit();

        const uint32_t base = sb + (uint32_t)(c % 3) * XG_STAGE;
        #pragma unroll
        for (int kk = 0; kk < CH; kk += 16) {
            uint32_t ra[4][4], rbh[2][4];
            #pragma unroll
            for (int mi = 0; mi < 4; ++mi) {
                uint32_t aa = base + (uint32_t)((a_row + mi * 16) * LDS_ + kk + a_col) * 2;
                ldm4(aa, ra[mi]);
            }
            #pragma unroll
            for (int nj = 0; nj < 2; ++nj) {
                uint32_t ba = base + 10240 + (uint32_t)((b_row + nj * 16) * LDS_ + kk + b_col) * 2;
                ldm4(ba, rbh[nj]);
            }
            #pragma unroll
            for (int mi = 0; mi < 4; ++mi) {
                #pragma unroll
                for (int b8 = 0; b8 < 4; ++b8) {
                    const uint32_t* bh = &rbh[b8 >> 1][(b8 & 1) * 2];
                    mma16816(acc[mi][b8], ra[mi], bh);
                }
            }
        }
    }
    #undef XLOAD

    #pragma unroll
    for (int mi = 0; mi < 4; ++mi) {
        #pragma unroll
        for (int h2 = 0; h2 < 2; ++h2) {
            const int r = m0 + mw + mi * 16 + (lane >> 2) + h2 * 8;
            float* dst = g_xg + (size_t)r * G_ + j0;
            #pragma unroll
            for (int ni = 0; ni < 4; ++ni) {
                const int cc = nw + ni * 8 + (lane & 3) * 2;
                float2 v = make_float2(acc[mi][ni][h2 * 2 + 0] + bias_s[cc],
                                       acc[mi][ni][h2 * 2 + 1] + bias_s[cc + 1]);
                *(float2*)(dst + cc) = v;
            }
        }
    }
}

// ---------------------------------------------------------------------------
// Step kernel body, templated on row count MT (96 or 64). 2-term recurrent
// split: h_hi*W_hi + h_lo*W_hi (W plain fp16; h hi/lo kept — h errors
// compound through the recurrence).
// CH=32, 3-stage pipeline + xg tile prefetched to smem (in stage-0's group).
// Stage (elems): Hhi[MT*40] Hlo[MT*40] Whi[64*40]
// smem map: [0 .. 3*STAGE_B)  pipeline stages (stage 0 reused for C staging)
//           [3*STAGE_B .. +MT*64*4)  xg tile [MT][64] fp32
// ---------------------------------------------------------------------------
#define STEP_SMEM (3 * ((2*96*LDS_ + 64*LDS_) * 2) + 96*64*4)   // 86016

template<int MT>
__device__ __forceinline__ void step_body(
    char* smem, uint32_t sb, int tid, int j0, int hb, int n0, int t,
    float* __restrict__ out)
{
    const int MI = MT / 32;
    const int STAGE_E = 2 * MT * LDS_ + 64 * LDS_;       // elems per stage
    const int STAGE_B = STAGE_E * 2;                     // bytes
    const int XGOFF   = 3 * STAGE_B;                     // xg tile offset (bytes)
    const int lane = tid & 31, wid = tid >> 5;
    const int wm = wid & 1, wn = wid >> 1;

    const int cur = t & 1, nxt = cur ^ 1;
    const __half* Hh = g_h_hi[cur] + (size_t)n0 * H_;
    const __half* Hl = g_h_lo[cur] + (size_t)n0 * H_;
    const __half* Wh = gWhh_hi + (size_t)j0 * KDIM;

    const int a_row = wm * (MI * 16) + (lane & 15);
    const int a_col = (lane >> 4) * 8;
    const int b_row = wn * 16 + ((lane >> 4) << 3) + (lane & 7);
    const int b_col = ((lane >> 3) & 1) * 8;

    float acc[MI > 2 ? 3 : 2][2][4];
    #pragma unroll
    for (int a = 0; a < MI; ++a)
        #pragma unroll
        for (int b = 0; b < 2; ++b)
            #pragma unroll
            for (int d = 0; d < 4; ++d) acc[a][b][d] = 0.0f;

    // chunk loader: MT rows h (hi+lo) + 64 rows W (hi only), 32 k each
    #define SLOAD(stg, kc) do {                                              \
        uint32_t _b = sb + (uint32_t)(stg) * STAGE_B;                        \
        _Pragma("unroll")                                                    \
        for (int u = tid; u < MT * 4; u += 256) {                            \
            int r_ = u >> 2, cg_ = (u & 3) * 8;                              \
            uint32_t d_ = _b + (uint32_t)(r_ * LDS_ + cg_) * 2;              \
            size_t g_ = (size_t)r_ * H_ + (kc) + cg_;                        \
            cp16(d_,                 Hh + g_);                               \
            cp16(d_ + MT * LDS_ * 2, Hl + g_);                               \
        }                                                                    \
        _Pragma("unroll")                                                    \
        for (int u = tid; u < 256; u += 256) {                               \
            int r_ = u >> 2, cg_ = (u & 3) * 8;                              \
            uint32_t d_ = _b + (uint32_t)(2 * MT * LDS_ + r_ * LDS_ + cg_) * 2; \
            cp16(d_, Wh + (size_t)r_ * KDIM + (kc) + cg_);                   \
        }                                                                    \
    } while (0)

    // group G0: stage 0 + the whole xg tile for this (tile, t)
    SLOAD(0, 0);
    #pragma unroll
    for (int u = tid; u < MT * 16; u += 256) {
        int r = u >> 4, cg = (u & 15) * 4;
        cp16(sb + XGOFF + (uint32_t)(r * 64 + cg) * 4,
             g_xg + ((size_t)(n0 + r) * T_ + t) * G_ + j0 + cg);
    }
    cp_commit();
    // group G1: stage 1
    SLOAD(1, CH);
    cp_commit();

    #pragma unroll 1
    for (int c = 0; c < NCHUNK; ++c) {
        cp_wait<1>();             // stage c (+xg if c==0) complete
        __syncthreads();          // all warps done with the buffer being refilled
        if (c + 2 < NCHUNK) SLOAD((c + 2) % 3, (c + 2) * CH);
        cp_commit();              // uniform accounting

        const uint32_t base = sb + (uint32_t)(c % 3) * STAGE_B;
        #pragma unroll
        for (int kk = 0; kk < CH; kk += 16) {
            uint32_t ra[MI > 2 ? 3 : 2][4], rl[MI > 2 ? 3 : 2][4], rbh[4];
            #pragma unroll
            for (int mi = 0; mi < MI; ++mi) {
                uint32_t aa = base + (uint32_t)((a_row + mi * 16) * LDS_ + kk + a_col) * 2;
                ldm4(aa, ra[mi]);
                ldm4(aa + MT * LDS_ * 2, rl[mi]);
            }
            uint32_t ba = base + (uint32_t)(2 * MT * LDS_ + b_row * LDS_ + kk + b_col) * 2;
            ldm4(ba, rbh);
            #pragma unroll
            for (int mi = 0; mi < MI; ++mi) {
                #pragma unroll
                for (int b8 = 0; b8 < 2; ++b8) {
                    const uint32_t* bhp = &rbh[b8 * 2];
                    mma16816(acc[mi][b8], ra[mi], bhp);   // hi*hi
                    mma16816(acc[mi][b8], rl[mi], bhp);   // lo*hi
                }
            }
        }
    }
    #undef SLOAD

    // all warps done reading stage buffers before C staging reuses stage 0
    __syncthreads();

    // stage C tile [MT][68] in smem (stage-0/1 region; xg tile untouched)
    float* Cs = (float*)smem;
    #pragma unroll
    for (int mi = 0; mi < MI; ++mi) {
        #pragma unroll
        for (int b8 = 0; b8 < 2; ++b8) {
            const int r = wm * (MI * 16) + mi * 16 + (lane >> 2);
            const int cc = wn * 16 + b8 * 8 + (lane & 3) * 2;
            *(float2*)&Cs[r * 68 + cc]       = make_float2(acc[mi][b8][0], acc[mi][b8][1]);
            *(float2*)&Cs[(r + 8) * 68 + cc] = make_float2(acc[mi][b8][2], acc[mi][b8][3]);
        }
    }
    __syncthreads();

    // fused LSTM cell update: MT/16 cells per thread; xg from smem
    const float* xgS = (const float*)(smem + XGOFF);
    const bool last = (t == T_ - 1);
    const int hl = tid & 15;
    const int rg = tid >> 4;
    #pragma unroll
    for (int e = 0; e < MT / 16; ++e) {
        const int r = rg + e * 16;
        const int gn = n0 + r;
        float4 cg = *(const float4*)&Cs[r * 68 + hl * 4];
        float4 xv = *(const float4*)&xgS[r * 64 + hl * 4];
        float ig = cg.x + xv.x, fg = cg.y + xv.y;
        float gg = cg.z + xv.z, og = cg.w + xv.w;

        float is = 1.0f / (1.0f + __expf(-ig));
        float fs = 1.0f / (1.0f + __expf(-fg));
        float gt = tanhf(gg);
        float os = 1.0f / (1.0f + __expf(-og));

        const size_t ci = (size_t)gn * H_ + hb + hl;
        float c = fs * g_c[ci] + is * gt;
        g_c[ci] = c;
        float hv = os * tanhf(c);
        if (last) {
            out[ci] = hv;
        } else {
            __half hi, lo;
            f2split(hv, hi, lo);
            g_h_hi[nxt][ci] = hi;
            g_h_lo[nxt][ci] = lo;
        }
    }
}

// ---------------------------------------------------------------------------
// Step kernel: 288 CTAs = 32 jb x 9 row-tiles (2x96 + 7x64 rows), single wave.
// ---------------------------------------------------------------------------
__global__ __launch_bounds__(256, 2)
void step_mma_kernel(float* __restrict__ out, int t) {
    extern __shared__ char smem[];
    const uint32_t sb = smem_u32_of(smem);
    const int tid = threadIdx.x;
    const int bid = blockIdx.x;
    const int nt = bid >> 5;          // 0..8 (row tile)
    const int jb = bid & 31;          // 0..31 (col block)
    const int j0 = jb * 64;
    const int hb = jb * 16;

    if (nt < 2) {
        step_body<96>(smem, sb, tid, j0, hb, nt * 96, t, out);
    } else {
        step_body<64>(smem, sb, tid, j0, hb, 192 + (nt - 2) * 64, t, out);
    }
}

// ---------------------------------------------------------------------------
// Launch
// ---------------------------------------------------------------------------
extern "C" void kernel_launch(void* const* d_in, const int* in_sizes, int n_in,
                              void* d_out, int out_size)
{
    const float* X   = (const float*)d_in[0];   // [B,Q,T,D] == [N*T, D]
    const float* Wih = (const float*)d_in[1];   // [4H, D]
    const float* Whh = (const float*)d_in[2];   // [4H, H]
    const float* bih = (const float*)d_in[3];   // [4H]
    const float* bhh = (const float*)d_in[4];   // [4H]
    float* out = (float*)d_out;                 // [B,Q,H] == [N, H]

    cudaFuncSetAttribute(xg_mma_kernel,   cudaFuncAttributeMaxDynamicSharedMemorySize, XG_SMEM);
    cudaFuncSetAttribute(step_mma_kernel, cudaFuncAttributeMaxDynamicSharedMemorySize, STEP_SMEM);

    init_state_kernel<<<(N_ * H_ + 255) / 256, 256>>>();
    conv_x_kernel<<<(int)(((size_t)M_ * KDIM / 4 + 255) / 256), 256>>>(X);
    conv_w_kernel<<<G_, 256>>>(Wih, Whh, bih, bhh);

    xg_mma_kernel<<<dim3(G_ / 128, M_ / 128), 256, XG_SMEM>>>();

    for (int t = 0; t < T_; ++t) {
        step_mma_kernel<<<288, 256, STEP_SMEM>>>(out, t);
    }
}

// round 17
// speedup vs baseline: 1.9009x; 1.0386x over previous
#include <cuda_runtime.h>
#include <cuda_fp16.h>
#include <stdint.h>
#include <math.h>

// Problem constants
#define B_   32
#define Q_   20
#define T_   100
#define KDIM 512          // D == H == 512 (GEMM K dim)
#define H_   512
#define N_   (B_*Q_)      // 640 sequences
#define G_   (4*H_)       // 2048 gate columns (interleaved: jp = h*4 + gate)
#define M_   (N_*T_)      // 64000 rows of the x_gates GEMM

#define LDS_   40         // smem row stride (fp16 elems) for 32-wide k-chunks
#define CH     32         // k-chunk
#define NCHUNK (KDIM/CH)  // 16

// ---------------------------------------------------------------------------
// Static device scratch
// ---------------------------------------------------------------------------
__device__ __align__(16) float  g_xg[(size_t)M_ * G_];      // interleaved gate pre-acts
__device__ __align__(16) __half gX_hi[(size_t)M_ * KDIM];   // X in plain fp16
__device__ __align__(16) __half gWih_hi[(size_t)G_ * KDIM]; // interleaved rows, plain fp16
__device__ __align__(16) __half gWhh_hi[(size_t)G_ * KDIM]; // interleaved rows, plain fp16
__device__ float g_biasI[G_];                               // interleaved bih+bhh
__device__ __align__(16) __half g_h_hi[2][(size_t)N_ * H_];
__device__ __align__(16) __half g_h_lo[2][(size_t)N_ * H_];
__device__ float g_c[(size_t)N_ * H_];

// ---------------------------------------------------------------------------
// PTX helpers
// ---------------------------------------------------------------------------
__device__ __forceinline__ uint32_t smem_u32_of(const void* p) {
    uint32_t a;
    asm("{ .reg .u64 t; cvta.to.shared.u64 t, %1; cvt.u32.u64 %0, t; }" : "=r"(a) : "l"(p));
    return a;
}
__device__ __forceinline__ void cp16(uint32_t dst, const void* src) {
    asm volatile("cp.async.cg.shared.global [%0], [%1], 16;" :: "r"(dst), "l"(src));
}
__device__ __forceinline__ void cp_commit() {
    asm volatile("cp.async.commit_group;" ::: "memory");
}
template<int NN> __device__ __forceinline__ void cp_wait() {
    asm volatile("cp.async.wait_group %0;" :: "n"(NN) : "memory");
}
__device__ __forceinline__ void ldm4(uint32_t addr, uint32_t* r) {
    asm volatile("ldmatrix.sync.aligned.m8n8.x4.shared.b16 {%0,%1,%2,%3}, [%4];"
        : "=r"(r[0]), "=r"(r[1]), "=r"(r[2]), "=r"(r[3]) : "r"(addr));
}
__device__ __forceinline__ void mma16816(float* c, const uint32_t* a, const uint32_t* b) {
    asm volatile("mma.sync.aligned.m16n8k16.row.col.f32.f16.f16.f32 "
        "{%0,%1,%2,%3}, {%4,%5,%6,%7}, {%8,%9}, {%0,%1,%2,%3};"
        : "+f"(c[0]), "+f"(c[1]), "+f"(c[2]), "+f"(c[3])
        : "r"(a[0]), "r"(a[1]), "r"(a[2]), "r"(a[3]), "r"(b[0]), "r"(b[1]));
}
__device__ __forceinline__ void f2split(float x, __half& hi, __half& lo) {
    hi = __float2half_rn(x);
    lo = __float2half_rn(x - __half2float(hi));
}

// ---------------------------------------------------------------------------
// Setup kernels
// ---------------------------------------------------------------------------
__global__ void init_state_kernel() {
    int idx = blockIdx.x * blockDim.x + threadIdx.x;
    if (idx < N_ * H_) {
        g_h_hi[0][idx] = __float2half_rn(0.0f);
        g_h_lo[0][idx] = __float2half_rn(0.0f);
        g_c[idx] = 0.0f;
    }
}

__global__ void conv_x_kernel(const float* __restrict__ X) {
    size_t base = ((size_t)blockIdx.x * blockDim.x + threadIdx.x) * 4;
    if (base < (size_t)M_ * KDIM) {
        float4 v = *(const float4*)(X + base);
        __half2 p0 = make_half2(__float2half_rn(v.x), __float2half_rn(v.y));
        __half2 p1 = make_half2(__float2half_rn(v.z), __float2half_rn(v.w));
        *(__half2*)(gX_hi + base)     = p0;
        *(__half2*)(gX_hi + base + 2) = p1;
    }
}

__global__ void conv_w_kernel(const float* __restrict__ Wih,
                              const float* __restrict__ Whh,
                              const float* __restrict__ bih,
                              const float* __restrict__ bhh) {
    int jp = blockIdx.x;                 // interleaved dst row 0..2047
    int gate = jp & 3, h = jp >> 2;
    int j = gate * H_ + h;               // source row
    const float* si = Wih + (size_t)j * KDIM;
    const float* sh = Whh + (size_t)j * KDIM;
    for (int k = threadIdx.x; k < KDIM; k += blockDim.x) {
        gWih_hi[(size_t)jp * KDIM + k] = __float2half_rn(si[k]);
        gWhh_hi[(size_t)jp * KDIM + k] = __float2half_rn(sh[k]);
    }
    if (threadIdx.x == 0) g_biasI[jp] = bih[j] + bhh[j];
}

// ---------------------------------------------------------------------------
// x_gates GEMM: 128x128 tile, grid (16, 500), 5-stage, 2 CTAs/SM.
// A = X plain fp16; B = W_ih plain fp16 (single-term).
// Stage (bytes): A[10240] Bh[10240] = 20480.
// ---------------------------------------------------------------------------
#define XG_STAGE 20480
#define XG_NSTG  5
#define XG_SMEM  (XG_STAGE * XG_NSTG)    // 102400

__global__ __launch_bounds__(256, 2)
void xg_mma_kernel() {
    extern __shared__ char smem[];
    const uint32_t sb = smem_u32_of(smem);
    __shared__ float bias_s[128];
    const int tid = threadIdx.x;
    const int j0 = blockIdx.x * 128;
    const int m0 = blockIdx.y * 128;
    if (tid < 128) bias_s[tid] = g_biasI[j0 + tid];

    const __half* Ah = gX_hi   + (size_t)m0 * KDIM;
    const __half* Bh = gWih_hi + (size_t)j0 * KDIM;

    const int lane = tid & 31, wid = tid >> 5;
    const int mw = (wid & 1) * 64, nw = (wid >> 1) * 32;
    const int a_row = mw + (lane & 15);
    const int a_col = (lane >> 4) * 8;
    const int b_row = nw + ((lane >> 4) << 3) + (lane & 7);
    const int b_col = ((lane >> 3) & 1) * 8;

    float acc[4][4][4];
    #pragma unroll
    for (int a = 0; a < 4; ++a)
        #pragma unroll
        for (int b = 0; b < 4; ++b)
            #pragma unroll
            for (int d = 0; d < 4; ++d) acc[a][b][d] = 0.0f;

    #define XLOAD(stg, kc) do {                                          \
        uint32_t _b = sb + (uint32_t)(stg) * XG_STAGE;                   \
        _Pragma("unroll")                                                \
        for (int u = tid; u < 512; u += 256) {                           \
            int r_ = u >> 2, cg_ = (u & 3) * 8;                          \
            cp16(_b + (uint32_t)(r_ * LDS_ + cg_) * 2,                   \
                 Ah + (size_t)r_ * KDIM + (kc) + cg_);                   \
            cp16(_b + 10240 + (uint32_t)(r_ * LDS_ + cg_) * 2,           \
                 Bh + (size_t)r_ * KDIM + (kc) + cg_);                   \
        }                                                                \
    } while (0)

    // prologue: stages 0..3
    XLOAD(0, 0);      cp_commit();
    XLOAD(1, CH);     cp_commit();
    XLOAD(2, 2 * CH); cp_commit();
    XLOAD(3, 3 * CH); cp_commit();

    #pragma unroll 1
    for (int c = 0; c < NCHUNK; ++c) {
        cp_wait<3>();            // chunk c complete
        __syncthreads();         // all warps done with the buffer being refilled
        if (c + 4 < NCHUNK) XLOAD((c + 4) % XG_NSTG, (c + 4) * CH);
        cp_commit();             // uniform accounting (possibly empty)

        const uint32_t base = sb + (uint32_t)(c % XG_NSTG) * XG_STAGE;
        #pragma unroll
        for (int kk = 0; kk < CH; kk += 16) {
            uint32_t ra[4][4], rbh[2][4];
            #pragma unroll
            for (int mi = 0; mi < 4; ++mi) {
                uint32_t aa = base + (uint32_t)((a_row + mi * 16) * LDS_ + kk + a_col) * 2;
                ldm4(aa, ra[mi]);
            }
            #pragma unroll
            for (int nj = 0; nj < 2; ++nj) {
                uint32_t ba = base + 10240 + (uint32_t)((b_row + nj * 16) * LDS_ + kk + b_col) * 2;
                ldm4(ba, rbh[nj]);
            }
            #pragma unroll
            for (int mi = 0; mi < 4; ++mi) {
                #pragma unroll
                for (int b8 = 0; b8 < 4; ++b8) {
                    const uint32_t* bh = &rbh[b8 >> 1][(b8 & 1) * 2];
                    mma16816(acc[mi][b8], ra[mi], bh);
                }
            }
        }
    }
    #undef XLOAD

    #pragma unroll
    for (int mi = 0; mi < 4; ++mi) {
        #pragma unroll
        for (int h2 = 0; h2 < 2; ++h2) {
            const int r = m0 + mw + mi * 16 + (lane >> 2) + h2 * 8;
            float* dst = g_xg + (size_t)r * G_ + j0;
            #pragma unroll
            for (int ni = 0; ni < 4; ++ni) {
                const int cc = nw + ni * 8 + (lane & 3) * 2;
                float2 v = make_float2(acc[mi][ni][h2 * 2 + 0] + bias_s[cc],
                                       acc[mi][ni][h2 * 2 + 1] + bias_s[cc + 1]);
                *(float2*)(dst + cc) = v;
            }
        }
    }
}

// ---------------------------------------------------------------------------
// Step kernel body, templated on row count MT (96 or 64). 2-term recurrent
// split: h_hi*W_hi + h_lo*W_hi. CH=32, 4-stage pipeline. Prefetches BOTH the
// xg tile AND the c tile into smem in stage-0's cp.async group, so the
// epilogue has no dependent gmem loads (c written back via STG).
// Stage (elems): Hhi[MT*40] Hlo[MT*40] Whi[64*40]
// smem map: [0 .. 4*STAGE_B)  stages (stage 0 reused for C staging)
//           [4*STAGE_B .. +MT*64*4)   xg tile [MT][64] fp32
//           [.. +MT*16*4)             c  tile [MT][16] fp32
// ---------------------------------------------------------------------------
#define STEP_SMEM (4 * ((2*96*LDS_ + 64*LDS_) * 2) + 96*64*4 + 96*16*4)  // 112640

template<int MT>
__device__ __forceinline__ void step_body(
    char* smem, uint32_t sb, int tid, int j0, int hb, int n0, int t,
    float* __restrict__ out)
{
    const int MI = MT / 32;
    const int STAGE_E = 2 * MT * LDS_ + 64 * LDS_;       // elems per stage
    const int STAGE_B = STAGE_E * 2;                     // bytes
    const int XGOFF   = 4 * STAGE_B;                     // xg tile offset (bytes)
    const int COFF    = XGOFF + MT * 64 * 4;             // c tile offset (bytes)
    const int lane = tid & 31, wid = tid >> 5;
    const int wm = wid & 1, wn = wid >> 1;

    const int cur = t & 1, nxt = cur ^ 1;
    const __half* Hh = g_h_hi[cur] + (size_t)n0 * H_;
    const __half* Hl = g_h_lo[cur] + (size_t)n0 * H_;
    const __half* Wh = gWhh_hi + (size_t)j0 * KDIM;

    const int a_row = wm * (MI * 16) + (lane & 15);
    const int a_col = (lane >> 4) * 8;
    const int b_row = wn * 16 + ((lane >> 4) << 3) + (lane & 7);
    const int b_col = ((lane >> 3) & 1) * 8;

    float acc[MI > 2 ? 3 : 2][2][4];
    #pragma unroll
    for (int a = 0; a < MI; ++a)
        #pragma unroll
        for (int b = 0; b < 2; ++b)
            #pragma unroll
            for (int d = 0; d < 4; ++d) acc[a][b][d] = 0.0f;

    // chunk loader: MT rows h (hi+lo) + 64 rows W (hi only), 32 k each
    #define SLOAD(stg, kc) do {                                              \
        uint32_t _b = sb + (uint32_t)(stg) * STAGE_B;                        \
        _Pragma("unroll")                                                    \
        for (int u = tid; u < MT * 4; u += 256) {                            \
            int r_ = u >> 2, cg_ = (u & 3) * 8;                              \
            uint32_t d_ = _b + (uint32_t)(r_ * LDS_ + cg_) * 2;              \
            size_t g_ = (size_t)r_ * H_ + (kc) + cg_;                        \
            cp16(d_,                 Hh + g_);                               \
            cp16(d_ + MT * LDS_ * 2, Hl + g_);                               \
        }                                                                    \
        _Pragma("unroll")                                                    \
        for (int u = tid; u < 256; u += 256) {                               \
            int r_ = u >> 2, cg_ = (u & 3) * 8;                              \
            uint32_t d_ = _b + (uint32_t)(2 * MT * LDS_ + r_ * LDS_ + cg_) * 2; \
            cp16(d_, Wh + (size_t)r_ * KDIM + (kc) + cg_);                   \
        }                                                                    \
    } while (0)

    // G0: stage 0 + xg tile + c tile
    SLOAD(0, 0);
    #pragma unroll
    for (int u = tid; u < MT * 16; u += 256) {
        int r = u >> 4, cg = (u & 15) * 4;
        cp16(sb + XGOFF + (uint32_t)(r * 64 + cg) * 4,
             g_xg + ((size_t)(n0 + r) * T_ + t) * G_ + j0 + cg);
    }
    #pragma unroll
    for (int u = tid; u < MT * 4; u += 256) {
        int r = u >> 2, cg = (u & 3) * 4;
        cp16(sb + COFF + (uint32_t)(r * 16 + cg) * 4,
             g_c + (size_t)(n0 + r) * H_ + hb + cg);
    }
    cp_commit();
    // G1, G2: stages 1, 2
    SLOAD(1, CH);     cp_commit();
    SLOAD(2, 2 * CH); cp_commit();

    #pragma unroll 1
    for (int c = 0; c < NCHUNK; ++c) {
        cp_wait<2>();             // chunk c (+xg/c tiles if c==0) complete
        __syncthreads();          // all warps done with the buffer being refilled
        if (c + 3 < NCHUNK) SLOAD((c + 3) & 3, (c + 3) * CH);
        cp_commit();              // uniform accounting

        const uint32_t base = sb + (uint32_t)(c & 3) * STAGE_B;
        #pragma unroll
        for (int kk = 0; kk < CH; kk += 16) {
            uint32_t ra[MI > 2 ? 3 : 2][4], rl[MI > 2 ? 3 : 2][4], rbh[4];
            #pragma unroll
            for (int mi = 0; mi < MI; ++mi) {
                uint32_t aa = base + (uint32_t)((a_row + mi * 16) * LDS_ + kk + a_col) * 2;
                ldm4(aa, ra[mi]);
                ldm4(aa + MT * LDS_ * 2, rl[mi]);
            }
            uint32_t ba = base + (uint32_t)(2 * MT * LDS_ + b_row * LDS_ + kk + b_col) * 2;
            ldm4(ba, rbh);
            #pragma unroll
            for (int mi = 0; mi < MI; ++mi) {
                #pragma unroll
                for (int b8 = 0; b8 < 2; ++b8) {
                    const uint32_t* bhp = &rbh[b8 * 2];
                    mma16816(acc[mi][b8], ra[mi], bhp);   // hi*hi
                    mma16816(acc[mi][b8], rl[mi], bhp);   // lo*hi
                }
            }
        }
    }
    #undef SLOAD

    // all warps done reading stage buffers before C staging reuses stage 0
    __syncthreads();

    // stage C tile [MT][68] in smem (stage region; xg/c tiles untouched)
    float* Cs = (float*)smem;
    #pragma unroll
    for (int mi = 0; mi < MI; ++mi) {
        #pragma unroll
        for (int b8 = 0; b8 < 2; ++b8) {
            const int r = wm * (MI * 16) + mi * 16 + (lane >> 2);
            const int cc = wn * 16 + b8 * 8 + (lane & 3) * 2;
            *(float2*)&Cs[r * 68 + cc]       = make_float2(acc[mi][b8][0], acc[mi][b8][1]);
            *(float2*)&Cs[(r + 8) * 68 + cc] = make_float2(acc[mi][b8][2], acc[mi][b8][3]);
        }
    }
    __syncthreads();

    // fused LSTM cell update: MT/16 cells per thread; xg AND c from smem
    const float* xgS = (const float*)(smem + XGOFF);
    const float* cS  = (const float*)(smem + COFF);
    const bool last = (t == T_ - 1);
    const int hl = tid & 15;
    const int rg = tid >> 4;
    #pragma unroll
    for (int e = 0; e < MT / 16; ++e) {
        const int r = rg + e * 16;
        const int gn = n0 + r;
        float4 cg = *(const float4*)&Cs[r * 68 + hl * 4];
        float4 xv = *(const float4*)&xgS[r * 64 + hl * 4];
        float ig = cg.x + xv.x, fg = cg.y + xv.y;
        float gg = cg.z + xv.z, og = cg.w + xv.w;

        float is = 1.0f / (1.0f + __expf(-ig));
        float fs = 1.0f / (1.0f + __expf(-fg));
        float gt = tanhf(gg);
        float os = 1.0f / (1.0f + __expf(-og));

        const size_t ci = (size_t)gn * H_ + hb + hl;
        float c = fs * cS[r * 16 + hl] + is * gt;
        g_c[ci] = c;
        float hv = os * tanhf(c);
        if (last) {
            out[ci] = hv;
        } else {
            __half hi, lo;
            f2split(hv, hi, lo);
            g_h_hi[nxt][ci] = hi;
            g_h_lo[nxt][ci] = lo;
        }
    }
}

// ---------------------------------------------------------------------------
// Step kernel: 288 CTAs = 32 jb x 9 row-tiles (2x96 + 7x64 rows), single wave.
// ---------------------------------------------------------------------------
__global__ __launch_bounds__(256, 2)
void step_mma_kernel(float* __restrict__ out, int t) {
    extern __shared__ char smem[];
    const uint32_t sb = smem_u32_of(smem);
    const int tid = threadIdx.x;
    const int bid = blockIdx.x;
    const int nt = bid >> 5;          // 0..8 (row tile)
    const int jb = bid & 31;          // 0..31 (col block)
    const int j0 = jb * 64;
    const int hb = jb * 16;

    if (nt < 2) {
        step_body<96>(smem, sb, tid, j0, hb, nt * 96, t, out);
    } else {
        step_body<64>(smem, sb, tid, j0, hb, 192 + (nt - 2) * 64, t, out);
    }
}

// ---------------------------------------------------------------------------
// Launch
// ---------------------------------------------------------------------------
extern "C" void kernel_launch(void* const* d_in, const int* in_sizes, int n_in,
                              void* d_out, int out_size)
{
    const float* X   = (const float*)d_in[0];   // [B,Q,T,D] == [N*T, D]
    const float* Wih = (const float*)d_in[1];   // [4H, D]
    const float* Whh = (const float*)d_in[2];   // [4H, H]
    const float* bih = (const float*)d_in[3];   // [4H]
    const float* bhh = (const float*)d_in[4];   // [4H]
    float* out = (float*)d_out;                 // [B,Q,H] == [N, H]

    cudaFuncSetAttribute(xg_mma_kernel,   cudaFuncAttributeMaxDynamicSharedMemorySize, XG_SMEM);
    cudaFuncSetAttribute(step_mma_kernel, cudaFuncAttributeMaxDynamicSharedMemorySize, STEP_SMEM);

    init_state_kernel<<<(N_ * H_ + 255) / 256, 256>>>();
    conv_x_kernel<<<(int)(((size_t)M_ * KDIM / 4 + 255) / 256), 256>>>(X);
    conv_w_kernel<<<G_, 256>>>(Wih, Whh, bih, bhh);

    xg_mma_kernel<<<dim3(G_ / 128, M_ / 128), 256, XG_SMEM>>>();

    for (int t = 0; t < T_; ++t) {
        step_mma_kernel<<<288, 256, STEP_SMEM>>>(out, t);
    }
}